// round 16
// baseline (speedup 1.0000x reference)
#include <cuda_runtime.h>
#include <cuda_bf16.h>
#include <cuda_fp16.h>

#define NB 4
#define NS 2048
#define NE 1024
#define NH 16
#define ND 64
#define NM (NB*NS)          // 8192 rows

// ---------------------------------------------------------------------------
// Device-global scratch (allocation-free rule). All fp16 singles.
// ---------------------------------------------------------------------------
__device__ __half g_x16[(size_t)NM*NE];
__device__ __half g_w16[(size_t)4*NE*NE];          // q,k,v,o
__device__ __half g_q16[(size_t)NM*NE];            // [B,H,S,D], pre-scaled
__device__ __half g_k16[(size_t)NM*NE];
__device__ __half g_v16[(size_t)NM*NE];
__device__ __half g_c16[(size_t)NM*NE];            // ctx [B,S,E]

// ---------------------------------------------------------------------------
// Helpers
// ---------------------------------------------------------------------------
__device__ __forceinline__ unsigned smem_u32(const void* p) {
    unsigned a;
    asm("{ .reg .u64 t; cvta.to.shared.u64 t, %1; cvt.u32.u64 %0, t; }"
        : "=r"(a) : "l"(p));
    return a;
}
#define SW128(o) ((o) ^ (((o) >> 3) & 0x70))

__device__ __forceinline__ void ldm4(unsigned* r, unsigned addr) {
    asm volatile("ldmatrix.sync.aligned.m8n8.x4.shared.b16 {%0,%1,%2,%3}, [%4];"
                 : "=r"(r[0]), "=r"(r[1]), "=r"(r[2]), "=r"(r[3]) : "r"(addr));
}
__device__ __forceinline__ void ldm4t(unsigned* r, unsigned addr) {
    asm volatile("ldmatrix.sync.aligned.m8n8.x4.trans.shared.b16 {%0,%1,%2,%3}, [%4];"
                 : "=r"(r[0]), "=r"(r[1]), "=r"(r[2]), "=r"(r[3]) : "r"(addr));
}
__device__ __forceinline__ void mma16816h(float* d, unsigned a0, unsigned a1,
                                          unsigned a2, unsigned a3,
                                          unsigned b0, unsigned b1) {
    asm volatile(
        "mma.sync.aligned.m16n8k16.row.col.f32.f16.f16.f32 "
        "{%0,%1,%2,%3}, {%4,%5,%6,%7}, {%8,%9}, {%0,%1,%2,%3};"
        : "+f"(d[0]), "+f"(d[1]), "+f"(d[2]), "+f"(d[3])
        : "r"(a0), "r"(a1), "r"(a2), "r"(a3), "r"(b0), "r"(b1));
}
#define CP_ASYNC16(dst, src) \
    asm volatile("cp.async.cg.shared.global [%0], [%1], 16;" :: "r"(dst), "l"(src))
#define CP_COMMIT() asm volatile("cp.async.commit_group;" ::: "memory")
#define CP_WAIT(n)  asm volatile("cp.async.wait_group %0;" :: "n"(n) : "memory")

__device__ __forceinline__ unsigned pack_h2(float a, float b) {
    __half2 t = __floats2half2_rn(a, b);
    return *(unsigned*)&t;
}
__device__ __forceinline__ float ex2(float x) {
    float y;
    asm("ex2.approx.f32 %0, %1;" : "=f"(y) : "f"(x));
    return y;
}

// ---------------------------------------------------------------------------
// fp32 -> fp16 conversions
// ---------------------------------------------------------------------------
__global__ __launch_bounds__(256)
void conv_x_kernel(const float* __restrict__ src)
{
    size_t i = ((size_t)blockIdx.x * 256 + threadIdx.x) * 4;
    float4 v = *(const float4*)(src + i);
    *(__half2*)(g_x16 + i)     = __floats2half2_rn(v.x, v.y);
    *(__half2*)(g_x16 + i + 2) = __floats2half2_rn(v.z, v.w);
}

__global__ __launch_bounds__(256)
void conv_w_kernel(const float* __restrict__ Wq, const float* __restrict__ Wk,
                   const float* __restrict__ Wv, const float* __restrict__ Wo)
{
    const float* src = (blockIdx.y == 0) ? Wq : (blockIdx.y == 1) ? Wk
                     : (blockIdx.y == 2) ? Wv : Wo;
    __half* dst = g_w16 + (size_t)blockIdx.y * NE * NE;
    size_t i = ((size_t)blockIdx.x * 256 + threadIdx.x) * 4;
    float4 v = *(const float4*)(src + i);
    *(__half2*)(dst + i)     = __floats2half2_rn(v.x, v.y);
    *(__half2*)(dst + i + 2) = __floats2half2_rn(v.z, v.w);
}

// ---------------------------------------------------------------------------
// mma.sync NT-GEMM: C[128x128] = A[128xK] @ W[128xK]^T, fp16 single-pass.
// 256 thr = 8 warps (4m x 2n), warp 32x64. BK=64. 3-stage cp.async pipeline.
// ---------------------------------------------------------------------------
#define MM_TILE  16384                 // 128 rows x 128 bytes (64 fp16/row)
#define MM_STAGE (2 * MM_TILE)         // A, B (32 KB)
#define MM_SMEM  (3 * MM_STAGE)        // 96 KB, 3 stages

__global__ __launch_bounds__(256, 1)
void mm_tc(int mode, const float* __restrict__ bias0, const float* __restrict__ bias1,
           const float* __restrict__ bias2, float* __restrict__ outp)
{
    extern __shared__ char sm[];
    const unsigned smb = smem_u32(sm);
    const int tid = threadIdx.x;
    const int lane = tid & 31, w = tid >> 5;
    const int wm = w & 3, wn = w >> 2;

    const int z  = (mode == 0) ? (int)blockIdx.z : 3;
    const int m0 = blockIdx.x * 128;
    const int n0 = blockIdx.y * 128;

    const __half* Ap = ((mode == 0) ? g_x16 : g_c16) + (size_t)m0 * NE;
    const __half* Bp = g_w16 + (size_t)z * NE * NE + (size_t)n0 * NE;

    float acc[2][8][4];
    #pragma unroll
    for (int mt = 0; mt < 2; mt++)
        #pragma unroll
        for (int nt = 0; nt < 8; nt++)
            #pragma unroll
            for (int q = 0; q < 4; q++) acc[mt][nt][q] = 0.f;

    auto load_chunk = [&](int buf, int k0) {
        const unsigned sb = smb + buf * MM_STAGE;
        #pragma unroll
        for (int i = 0; i < 4; i++) {
            int e = tid + i * 256;
            int r = e >> 3, c = e & 7;
            unsigned so = SW128(r * 128 + c * 16);
            CP_ASYNC16(sb + so, Ap + (size_t)r * NE + k0 + c * 8);
            CP_ASYNC16(sb + MM_TILE + so, Bp + (size_t)r * NE + k0 + c * 8);
        }
    };

    load_chunk(0, 0);    CP_COMMIT();
    load_chunk(1, 64);   CP_COMMIT();
    load_chunk(2, 128);  CP_COMMIT();

    int st = 0;
    #pragma unroll 1
    for (int ch = 0; ch < 16; ch++) {
        CP_WAIT(2);
        __syncthreads();

        const unsigned ab = smb + st * MM_STAGE;
        #pragma unroll
        for (int ks = 0; ks < 4; ks++) {
            const unsigned kb = ks * 32 + ((lane >> 4) << 4);
            unsigned ah[2][4];
            #pragma unroll
            for (int mt = 0; mt < 2; mt++) {
                unsigned row = wm * 32 + mt * 16 + (lane & 15);
                ldm4(ah[mt], ab + SW128(row * 128 + kb));
            }
            unsigned b0[8], b1[8];
            #pragma unroll
            for (int np = 0; np < 4; np++) {
                unsigned row = wn * 64 + np * 16 + (lane & 15);
                unsigned r[4];
                ldm4(r, ab + MM_TILE + SW128(row * 128 + kb));
                b0[2*np] = r[0]; b1[2*np] = r[2];
                b0[2*np+1] = r[1]; b1[2*np+1] = r[3];
            }
            #pragma unroll
            for (int mt = 0; mt < 2; mt++)
                #pragma unroll
                for (int nt = 0; nt < 8; nt++)
                    mma16816h(acc[mt][nt], ah[mt][0], ah[mt][1], ah[mt][2], ah[mt][3],
                              b0[nt], b1[nt]);
        }

        __syncthreads();
        if (ch + 3 < 16) load_chunk(st, (ch + 3) * 64);
        CP_COMMIT();
        st = (st == 2) ? 0 : st + 1;
    }

    // scale folded into Q: S*log2e/sqrt(d) done here once
    const float qscale = (mode == 0 && z == 0) ? (0.125f * 1.44269504088896f) : 1.0f;

    const int g = lane >> 2, c4 = lane & 3;
    #pragma unroll
    for (int mt = 0; mt < 2; mt++) {
        #pragma unroll
        for (int nt = 0; nt < 8; nt++) {
            const int n = n0 + wn * 64 + nt * 8 + 2 * c4;
            const float2 b2 = *(const float2*)&((mode == 1) ? bias0
                                : (z == 0) ? bias0 : (z == 1) ? bias1 : bias2)[n];
            #pragma unroll
            for (int hrow = 0; hrow < 2; hrow++) {
                const int m = m0 + wm * 32 + mt * 16 + g + hrow * 8;
                float v0 = acc[mt][nt][2*hrow + 0] + b2.x;
                float v1 = acc[mt][nt][2*hrow + 1] + b2.y;
                if (mode == 1) {
                    *(float2*)&outp[(size_t)m * NE + n] = make_float2(v0, v1);
                } else {
                    v0 *= qscale; v1 *= qscale;
                    const int bb = m >> 11, s = m & (NS - 1);
                    const int hh = n >> 6, d = n & 63;
                    size_t idx = (((size_t)(bb * NH + hh)) * NS + s) * ND + d;
                    __half* hp = (z == 0) ? g_q16 : (z == 1) ? g_k16 : g_v16;
                    *(__half2*)&hp[idx] = __floats2half2_rn(v0, v1);
                }
            }
        }
    }
}

// ---------------------------------------------------------------------------
// Flash attention, fp16 single path, WIDE warp tiles: 8 warps x 32 q-rows
// = 256 q-rows per CTA (grid 512). Each K/V fragment load feeds 2x MMAs.
// fp32 ex2 softmax (error margin restored), p packed fp16 for PV + ones-MMA
// l (same values -> num/denom cancellation). Q pre-scaled. 3-stage cp.async.
// ---------------------------------------------------------------------------
#define AT_Q  0                        // 32 KB fp16 Q (256 x 128B)
#define AT_KV 32768
#define AT_KVSTAGE 16384               // K 8KB + V 8KB
#define AT_MASK (AT_KV + 3 * AT_KVSTAGE)
#define AT_SMEM (AT_MASK + 3 * 256 + 16)

__global__ __launch_bounds__(256, 1)
void attn_kernel(const int* __restrict__ amask)
{
    extern __shared__ char sm[];
    const unsigned smb = smem_u32(sm);

    const int tid = threadIdx.x;
    const int lane = tid & 31, w = tid >> 5;
    const int g = lane >> 2, c4 = lane & 3;
    const int b = blockIdx.z, h = blockIdx.y;
    const int q0 = blockIdx.x * 256;

    const size_t bh_off = ((size_t)(b * NH + h)) * NS * ND;
    const __half* Qg = g_q16 + bh_off + (size_t)q0 * ND;
    const __half* KVp[2] = { g_k16 + bh_off, g_v16 + bh_off };
    const int* amp = amask + b * NS;

    auto issue_kv = [&](int stage, int k0) {
        const unsigned sb = smb + AT_KV + stage * AT_KVSTAGE;
        #pragma unroll
        for (int t = 0; t < 2; t++)
            #pragma unroll
            for (int i = 0; i < 2; i++) {
                int e = tid + i * 256;
                int r = e >> 3, c = e & 7;
                CP_ASYNC16(sb + t * 8192 + SW128(r * 128 + c * 16),
                           KVp[t] + (size_t)(k0 + r) * 64 + c * 8);
            }
        if (tid < 16)
            CP_ASYNC16(smb + AT_MASK + stage * 256 + tid * 16,
                       amp + k0 + tid * 4);
    };

    issue_kv(0, 0);    CP_COMMIT();
    issue_kv(1, 64);   CP_COMMIT();
    issue_kv(2, 128);  CP_COMMIT();

    // load Q (256 rows x 128B fp16 = 32 KB)
    #pragma unroll
    for (int i = 0; i < 8; i++) {
        int e = tid + i * 256;
        int r = e >> 3, c = e & 7;
        *(uint4*)(sm + AT_Q + SW128(r * 128 + c * 16)) =
            *(const uint4*)(Qg + (size_t)r * 64 + c * 8);
    }
    __syncthreads();

    // hoist Q fragments (loop-invariant): 2 mt x 4 ks x 4 regs
    unsigned qf[2][4][4];
    #pragma unroll
    for (int mt = 0; mt < 2; mt++) {
        const unsigned qrow = w * 32 + mt * 16 + (lane & 15);
        #pragma unroll
        for (int ks = 0; ks < 4; ks++) {
            const unsigned kb = ks * 32 + ((lane >> 4) << 4);
            ldm4(qf[mt][ks], smb + AT_Q + SW128(qrow * 128 + kb));
        }
    }

    const unsigned ONES = 0x3C003C00u;     // fp16x2 {1,1}
    float lacc[2][4] = {{0.f,0.f,0.f,0.f},{0.f,0.f,0.f,0.f}};
    float o[2][8][4];
    #pragma unroll
    for (int mt = 0; mt < 2; mt++)
        #pragma unroll
        for (int nt = 0; nt < 8; nt++)
            #pragma unroll
            for (int q = 0; q < 4; q++) o[mt][nt][q] = 0.f;

    int st = 0;
    #pragma unroll 1
    for (int kt = 0; kt < NS / 64; kt++) {
        const unsigned kvb = smb + AT_KV + st * AT_KVSTAGE;
        CP_WAIT(2);
        __syncthreads();

        // ---- S = Q K^T (both m-tiles share each B fragment) ----
        float s[2][8][4];
        #pragma unroll
        for (int mt = 0; mt < 2; mt++)
            #pragma unroll
            for (int nt = 0; nt < 8; nt++)
                #pragma unroll
                for (int q = 0; q < 4; q++) s[mt][nt][q] = 0.f;

        #pragma unroll
        for (int ks = 0; ks < 4; ks++) {
            const unsigned kb = ks * 32 + ((lane >> 4) << 4);
            unsigned b0[8], b1[8];
            #pragma unroll
            for (int np = 0; np < 4; np++) {
                unsigned nrow = np * 16 + (lane & 15);
                unsigned r[4];
                ldm4(r, kvb + SW128(nrow * 128 + kb));
                b0[2*np] = r[0]; b1[2*np] = r[2];
                b0[2*np+1] = r[1]; b1[2*np+1] = r[3];
            }
            #pragma unroll
            for (int mt = 0; mt < 2; mt++)
                #pragma unroll
                for (int nt = 0; nt < 8; nt++)
                    mma16816h(s[mt][nt], qf[mt][ks][0], qf[mt][ks][1],
                              qf[mt][ks][2], qf[mt][ks][3], b0[nt], b1[nt]);
        }

        // ---- softmax: p = ex2.f32(S + mask), pack fp16 ----
        const int* smask = (const int*)(sm + AT_MASK + st * 256);
        unsigned pg[2][8], pg8[2][8];
        #pragma unroll
        for (int nt = 0; nt < 8; nt++) {
            int2 mi = *(const int2*)&smask[nt * 8 + 2 * c4];
            float mA = mi.x ? 0.f : -1e30f;
            float mB = mi.y ? 0.f : -1e30f;
            #pragma unroll
            for (int mt = 0; mt < 2; mt++) {
                float p0 = ex2(s[mt][nt][0] + mA);
                float p1 = ex2(s[mt][nt][1] + mB);
                float p2 = ex2(s[mt][nt][2] + mA);
                float p3 = ex2(s[mt][nt][3] + mB);
                pg[mt][nt]  = pack_h2(p0, p1);
                pg8[mt][nt] = pack_h2(p2, p3);
            }
        }

        // ---- O += P V, l += P 1 (V fragments shared by both m-tiles) ----
        #pragma unroll
        for (int j = 0; j < 4; j++) {
            unsigned v0[8], v1[8];
            #pragma unroll
            for (int dp = 0; dp < 4; dp++) {
                unsigned krow = j * 16 + (lane & 7) + ((lane >> 4) << 3);
                unsigned dby  = dp * 32 + (((lane >> 3) & 1) << 4);
                unsigned r[4];
                ldm4t(r, kvb + 8192 + SW128(krow * 128 + dby));
                v0[2*dp] = r[0]; v1[2*dp] = r[2];
                v0[2*dp+1] = r[1]; v1[2*dp+1] = r[3];
            }
            #pragma unroll
            for (int mt = 0; mt < 2; mt++) {
                #pragma unroll
                for (int nt = 0; nt < 8; nt++)
                    mma16816h(o[mt][nt], pg[mt][2*j], pg8[mt][2*j],
                              pg[mt][2*j+1], pg8[mt][2*j+1], v0[nt], v1[nt]);
                mma16816h(lacc[mt], pg[mt][2*j], pg8[mt][2*j],
                          pg[mt][2*j+1], pg8[mt][2*j+1], ONES, ONES);
            }
        }

        __syncthreads();
        if (kt + 3 < NS / 64) issue_kv(st, (kt + 3) * 64);
        CP_COMMIT();
        st = (st == 2) ? 0 : st + 1;
    }

    // ---- finalize: l fully reduced by ones-MMA ----
    #pragma unroll
    for (int mt = 0; mt < 2; mt++) {
        const float inv0 = 1.0f / lacc[mt][0];
        const float inv1 = 1.0f / lacc[mt][2];
        const int qg = q0 + w * 32 + mt * 16 + g;
        #pragma unroll
        for (int nt = 0; nt < 8; nt++) {
            const int col = h * ND + nt * 8 + 2 * c4;
            *(__half2*)&g_c16[((size_t)(b * NS + qg)) * NE + col] =
                __floats2half2_rn(o[mt][nt][0] * inv0, o[mt][nt][1] * inv0);
            *(__half2*)&g_c16[((size_t)(b * NS + qg + 8)) * NE + col] =
                __floats2half2_rn(o[mt][nt][2] * inv1, o[mt][nt][3] * inv1);
        }
    }
}

// ---------------------------------------------------------------------------

extern "C" void kernel_launch(void* const* d_in, const int* in_sizes, int n_in,
                              void* d_out, int out_size)
{
    const float* x   = (const float*)d_in[0];
    const int*   am  = (const int*)  d_in[1];
    const float* Wq  = (const float*)d_in[2];
    const float* bq  = (const float*)d_in[3];
    const float* Wk  = (const float*)d_in[4];
    const float* bk  = (const float*)d_in[5];
    const float* Wv  = (const float*)d_in[6];
    const float* bv  = (const float*)d_in[7];
    const float* Wo  = (const float*)d_in[8];
    const float* bo  = (const float*)d_in[9];
    float* out = (float*)d_out;

    cudaFuncSetAttribute(mm_tc, cudaFuncAttributeMaxDynamicSharedMemorySize, MM_SMEM);
    cudaFuncSetAttribute(attn_kernel, cudaFuncAttributeMaxDynamicSharedMemorySize, AT_SMEM);

    conv_x_kernel<<<NM * NE / 1024, 256>>>(x);
    conv_w_kernel<<<dim3(NE * NE / 1024, 4), 256>>>(Wq, Wk, Wv, Wo);

    mm_tc<<<dim3(NM / 128, NE / 128, 3), 256, MM_SMEM>>>(0, bq, bk, bv, nullptr);

    attn_kernel<<<dim3(NS / 256, NH, NB), 256, AT_SMEM>>>(am);

    mm_tc<<<dim3(NM / 128, NE / 128, 1), 256, MM_SMEM>>>(1, bo, nullptr, nullptr, out);
}

// round 17
// speedup vs baseline: 1.5136x; 1.5136x over previous
#include <cuda_runtime.h>
#include <cuda_bf16.h>
#include <cuda_fp16.h>

#define NB 4
#define NS 2048
#define NE 1024
#define NH 16
#define ND 64
#define NM (NB*NS)          // 8192 rows

// ---------------------------------------------------------------------------
// Device-global scratch (allocation-free rule). All fp16 singles.
// ---------------------------------------------------------------------------
__device__ __half g_x16[(size_t)NM*NE];
__device__ __half g_w16[(size_t)4*NE*NE];          // q,k,v,o
__device__ __half g_q16[(size_t)NM*NE];            // [B,H,S,D], pre-scaled
__device__ __half g_k16[(size_t)NM*NE];
__device__ __half g_v16[(size_t)NM*NE];
__device__ __half g_c16[(size_t)NM*NE];            // ctx [B,S,E]

// ---------------------------------------------------------------------------
// Helpers
// ---------------------------------------------------------------------------
__device__ __forceinline__ unsigned smem_u32(const void* p) {
    unsigned a;
    asm("{ .reg .u64 t; cvta.to.shared.u64 t, %1; cvt.u32.u64 %0, t; }"
        : "=r"(a) : "l"(p));
    return a;
}
#define SW128(o) ((o) ^ (((o) >> 3) & 0x70))

__device__ __forceinline__ void ldm4(unsigned* r, unsigned addr) {
    asm volatile("ldmatrix.sync.aligned.m8n8.x4.shared.b16 {%0,%1,%2,%3}, [%4];"
                 : "=r"(r[0]), "=r"(r[1]), "=r"(r[2]), "=r"(r[3]) : "r"(addr));
}
__device__ __forceinline__ void ldm4t(unsigned* r, unsigned addr) {
    asm volatile("ldmatrix.sync.aligned.m8n8.x4.trans.shared.b16 {%0,%1,%2,%3}, [%4];"
                 : "=r"(r[0]), "=r"(r[1]), "=r"(r[2]), "=r"(r[3]) : "r"(addr));
}
__device__ __forceinline__ void mma16816h(float* d, unsigned a0, unsigned a1,
                                          unsigned a2, unsigned a3,
                                          unsigned b0, unsigned b1) {
    asm volatile(
        "mma.sync.aligned.m16n8k16.row.col.f32.f16.f16.f32 "
        "{%0,%1,%2,%3}, {%4,%5,%6,%7}, {%8,%9}, {%0,%1,%2,%3};"
        : "+f"(d[0]), "+f"(d[1]), "+f"(d[2]), "+f"(d[3])
        : "r"(a0), "r"(a1), "r"(a2), "r"(a3), "r"(b0), "r"(b1));
}
#define CP_ASYNC16(dst, src) \
    asm volatile("cp.async.cg.shared.global [%0], [%1], 16;" :: "r"(dst), "l"(src))
#define CP_COMMIT() asm volatile("cp.async.commit_group;" ::: "memory")
#define CP_WAIT(n)  asm volatile("cp.async.wait_group %0;" :: "n"(n) : "memory")

__device__ __forceinline__ unsigned pack_h2(float a, float b) {
    __half2 t = __floats2half2_rn(a, b);
    return *(unsigned*)&t;
}
__device__ __forceinline__ float ex2(float x) {
    float y;
    asm("ex2.approx.f32 %0, %1;" : "=f"(y) : "f"(x));
    return y;
}

// ---------------------------------------------------------------------------
// fp32 -> fp16 conversions
// ---------------------------------------------------------------------------
__global__ __launch_bounds__(256)
void conv_x_kernel(const float* __restrict__ src)
{
    size_t i = ((size_t)blockIdx.x * 256 + threadIdx.x) * 4;
    float4 v = *(const float4*)(src + i);
    *(__half2*)(g_x16 + i)     = __floats2half2_rn(v.x, v.y);
    *(__half2*)(g_x16 + i + 2) = __floats2half2_rn(v.z, v.w);
}

__global__ __launch_bounds__(256)
void conv_w_kernel(const float* __restrict__ Wq, const float* __restrict__ Wk,
                   const float* __restrict__ Wv, const float* __restrict__ Wo)
{
    const float* src = (blockIdx.y == 0) ? Wq : (blockIdx.y == 1) ? Wk
                     : (blockIdx.y == 2) ? Wv : Wo;
    __half* dst = g_w16 + (size_t)blockIdx.y * NE * NE;
    size_t i = ((size_t)blockIdx.x * 256 + threadIdx.x) * 4;
    float4 v = *(const float4*)(src + i);
    *(__half2*)(dst + i)     = __floats2half2_rn(v.x, v.y);
    *(__half2*)(dst + i + 2) = __floats2half2_rn(v.z, v.w);
}

// ---------------------------------------------------------------------------
// mma.sync NT-GEMM: C[128x128] = A[128xK] @ W[128xK]^T, fp16 single-pass.
// 256 thr = 8 warps (4m x 2n), warp 32x64. BK=128 (two 64-col sub-tiles per
// stage -> 8 mainloop iterations, half the sync/wait overhead). 3 stages.
// ---------------------------------------------------------------------------
#define MM_TILE  16384                 // 128 rows x 128 bytes (64 fp16)
#define MM_STAGE (4 * MM_TILE)         // A0,A1,B0,B1 (64 KB) = BK 128
#define MM_SMEM  (3 * MM_STAGE)        // 192 KB, 3 stages

__global__ __launch_bounds__(256, 1)
void mm_tc(int mode, const float* __restrict__ bias0, const float* __restrict__ bias1,
           const float* __restrict__ bias2, float* __restrict__ outp)
{
    extern __shared__ char sm[];
    const unsigned smb = smem_u32(sm);
    const int tid = threadIdx.x;
    const int lane = tid & 31, w = tid >> 5;
    const int wm = w & 3, wn = w >> 2;

    const int z  = (mode == 0) ? (int)blockIdx.z : 3;
    const int m0 = blockIdx.x * 128;
    const int n0 = blockIdx.y * 128;

    const __half* Ap = ((mode == 0) ? g_x16 : g_c16) + (size_t)m0 * NE;
    const __half* Bp = g_w16 + (size_t)z * NE * NE + (size_t)n0 * NE;

    float acc[2][8][4];
    #pragma unroll
    for (int mt = 0; mt < 2; mt++)
        #pragma unroll
        for (int nt = 0; nt < 8; nt++)
            #pragma unroll
            for (int q = 0; q < 4; q++) acc[mt][nt][q] = 0.f;

    // stage layout: [A(k0..63)][A(k64..127)][B(k0..63)][B(k64..127)]
    auto load_chunk = [&](int buf, int k0) {
        const unsigned sb = smb + buf * MM_STAGE;
        #pragma unroll
        for (int half = 0; half < 2; half++)
            #pragma unroll
            for (int i = 0; i < 4; i++) {
                int e = tid + i * 256;
                int r = e >> 3, c = e & 7;
                unsigned so = SW128(r * 128 + c * 16) + half * MM_TILE;
                CP_ASYNC16(sb + so,
                           Ap + (size_t)r * NE + k0 + half * 64 + c * 8);
                CP_ASYNC16(sb + 2 * MM_TILE + so,
                           Bp + (size_t)r * NE + k0 + half * 64 + c * 8);
            }
    };

    load_chunk(0, 0);    CP_COMMIT();
    load_chunk(1, 128);  CP_COMMIT();
    load_chunk(2, 256);  CP_COMMIT();

    int st = 0;
    #pragma unroll 1
    for (int ch = 0; ch < 8; ch++) {
        CP_WAIT(2);
        __syncthreads();

        const unsigned ab = smb + st * MM_STAGE;
        #pragma unroll
        for (int ks = 0; ks < 8; ks++) {
            const unsigned sub = (ks >> 2) * MM_TILE;
            const unsigned kb = (ks & 3) * 32 + ((lane >> 4) << 4);
            unsigned ah[2][4];
            #pragma unroll
            for (int mt = 0; mt < 2; mt++) {
                unsigned row = wm * 32 + mt * 16 + (lane & 15);
                ldm4(ah[mt], ab + sub + SW128(row * 128 + kb));
            }
            unsigned b0[8], b1[8];
            #pragma unroll
            for (int np = 0; np < 4; np++) {
                unsigned row = wn * 64 + np * 16 + (lane & 15);
                unsigned r[4];
                ldm4(r, ab + 2 * MM_TILE + sub + SW128(row * 128 + kb));
                b0[2*np] = r[0]; b1[2*np] = r[2];
                b0[2*np+1] = r[1]; b1[2*np+1] = r[3];
            }
            #pragma unroll
            for (int mt = 0; mt < 2; mt++)
                #pragma unroll
                for (int nt = 0; nt < 8; nt++)
                    mma16816h(acc[mt][nt], ah[mt][0], ah[mt][1], ah[mt][2], ah[mt][3],
                              b0[nt], b1[nt]);
        }

        __syncthreads();
        if (ch + 3 < 8) load_chunk(st, (ch + 3) * 128);
        CP_COMMIT();
        st = (st == 2) ? 0 : st + 1;
    }

    // scale folded into Q: S*log2e/sqrt(d) done here once
    const float qscale = (mode == 0 && z == 0) ? (0.125f * 1.44269504088896f) : 1.0f;

    const int g = lane >> 2, c4 = lane & 3;
    #pragma unroll
    for (int mt = 0; mt < 2; mt++) {
        #pragma unroll
        for (int nt = 0; nt < 8; nt++) {
            const int n = n0 + wn * 64 + nt * 8 + 2 * c4;
            const float2 b2 = *(const float2*)&((mode == 1) ? bias0
                                : (z == 0) ? bias0 : (z == 1) ? bias1 : bias2)[n];
            #pragma unroll
            for (int hrow = 0; hrow < 2; hrow++) {
                const int m = m0 + wm * 32 + mt * 16 + g + hrow * 8;
                float v0 = acc[mt][nt][2*hrow + 0] + b2.x;
                float v1 = acc[mt][nt][2*hrow + 1] + b2.y;
                if (mode == 1) {
                    *(float2*)&outp[(size_t)m * NE + n] = make_float2(v0, v1);
                } else {
                    v0 *= qscale; v1 *= qscale;
                    const int bb = m >> 11, s = m & (NS - 1);
                    const int hh = n >> 6, d = n & 63;
                    size_t idx = (((size_t)(bb * NH + hh)) * NS + s) * ND + d;
                    __half* hp = (z == 0) ? g_q16 : (z == 1) ? g_k16 : g_v16;
                    *(__half2*)&hp[idx] = __floats2half2_rn(v0, v1);
                }
            }
        }
    }
}

// ---------------------------------------------------------------------------
// Flash attention (R14 shape): 256 thr = 8 warps, 16 q-rows/warp, k-tiles 64.
// fp32 ex2 softmax (Q pre-scaled -> just add mask), p packed fp16,
// l via ones-column MMA on the same fp16 P (num/denom cancellation, no
// end shuffle reduce). 3-stage cp.async K/V pipeline. ctx -> fp16.
// ---------------------------------------------------------------------------
#define AT_Q  0                        // 16 KB fp16 Q (128 x 128B)
#define AT_KV 16384
#define AT_KVSTAGE 16384               // K 8KB + V 8KB
#define AT_MASK (AT_KV + 3 * AT_KVSTAGE)
#define AT_SMEM (AT_MASK + 3 * 256 + 16)

__global__ __launch_bounds__(256, 1)
void attn_kernel(const int* __restrict__ amask)
{
    extern __shared__ char sm[];
    const unsigned smb = smem_u32(sm);

    const int tid = threadIdx.x;
    const int lane = tid & 31, w = tid >> 5;
    const int g = lane >> 2, c4 = lane & 3;
    const int b = blockIdx.z, h = blockIdx.y;
    const int q0 = blockIdx.x * 128;

    const size_t bh_off = ((size_t)(b * NH + h)) * NS * ND;
    const __half* Qg = g_q16 + bh_off + (size_t)q0 * ND;
    const __half* KVp[2] = { g_k16 + bh_off, g_v16 + bh_off };
    const int* amp = amask + b * NS;

    auto issue_kv = [&](int stage, int k0) {
        const unsigned sb = smb + AT_KV + stage * AT_KVSTAGE;
        #pragma unroll
        for (int t = 0; t < 2; t++)
            #pragma unroll
            for (int i = 0; i < 2; i++) {
                int e = tid + i * 256;
                int r = e >> 3, c = e & 7;
                CP_ASYNC16(sb + t * 8192 + SW128(r * 128 + c * 16),
                           KVp[t] + (size_t)(k0 + r) * 64 + c * 8);
            }
        if (tid < 16)
            CP_ASYNC16(smb + AT_MASK + stage * 256 + tid * 16,
                       amp + k0 + tid * 4);
    };

    issue_kv(0, 0);    CP_COMMIT();
    issue_kv(1, 64);   CP_COMMIT();
    issue_kv(2, 128);  CP_COMMIT();

    // load Q (128 rows x 128B fp16)
    #pragma unroll
    for (int i = 0; i < 4; i++) {
        int e = tid + i * 256;
        int r = e >> 3, c = e & 7;
        *(uint4*)(sm + AT_Q + SW128(r * 128 + c * 16)) =
            *(const uint4*)(Qg + (size_t)r * 64 + c * 8);
    }
    __syncthreads();

    // hoist Q fragments (loop-invariant): 4 ks x 4 regs
    unsigned qf[4][4];
    {
        const unsigned qrow = w * 16 + (lane & 15);
        #pragma unroll
        for (int ks = 0; ks < 4; ks++) {
            const unsigned kb = ks * 32 + ((lane >> 4) << 4);
            ldm4(qf[ks], smb + AT_Q + SW128(qrow * 128 + kb));
        }
    }

    const unsigned ONES = 0x3C003C00u;     // fp16x2 {1,1}
    float lacc[4] = {0.f, 0.f, 0.f, 0.f};  // ones-column row sums
    float o[8][4];
    #pragma unroll
    for (int nt = 0; nt < 8; nt++)
        #pragma unroll
        for (int q = 0; q < 4; q++) o[nt][q] = 0.f;

    int st = 0;
    #pragma unroll 1
    for (int kt = 0; kt < NS / 64; kt++) {
        const unsigned kvb = smb + AT_KV + st * AT_KVSTAGE;
        CP_WAIT(2);
        __syncthreads();

        // ---- S = Q K^T (fp16 single pass; Q pre-scaled) ----
        float s[8][4];
        #pragma unroll
        for (int nt = 0; nt < 8; nt++)
            #pragma unroll
            for (int q = 0; q < 4; q++) s[nt][q] = 0.f;

        #pragma unroll
        for (int ks = 0; ks < 4; ks++) {
            const unsigned kb = ks * 32 + ((lane >> 4) << 4);
            unsigned b0[8], b1[8];
            #pragma unroll
            for (int np = 0; np < 4; np++) {
                unsigned nrow = np * 16 + (lane & 15);
                unsigned r[4];
                ldm4(r, kvb + SW128(nrow * 128 + kb));
                b0[2*np] = r[0]; b1[2*np] = r[2];
                b0[2*np+1] = r[1]; b1[2*np+1] = r[3];
            }
            #pragma unroll
            for (int nt = 0; nt < 8; nt++)
                mma16816h(s[nt], qf[ks][0], qf[ks][1], qf[ks][2], qf[ks][3],
                          b0[nt], b1[nt]);
        }

        // ---- softmax: p = ex2.f32(S + mask), pack fp16 ----
        const int* smask = (const int*)(sm + AT_MASK + st * 256);
        unsigned pg[8], pg8[8];
        #pragma unroll
        for (int nt = 0; nt < 8; nt++) {
            int2 mi = *(const int2*)&smask[nt * 8 + 2 * c4];
            float mA = mi.x ? 0.f : -1e30f;
            float mB = mi.y ? 0.f : -1e30f;
            float p0 = ex2(s[nt][0] + mA);
            float p1 = ex2(s[nt][1] + mB);
            float p2 = ex2(s[nt][2] + mA);
            float p3 = ex2(s[nt][3] + mB);
            pg[nt]  = pack_h2(p0, p1);
            pg8[nt] = pack_h2(p2, p3);
        }

        // ---- O += P V, l += P 1 (fp16 single pass) ----
        #pragma unroll
        for (int j = 0; j < 4; j++) {
            unsigned v0[8], v1[8];
            #pragma unroll
            for (int dp = 0; dp < 4; dp++) {
                unsigned krow = j * 16 + (lane & 7) + ((lane >> 4) << 3);
                unsigned dby  = dp * 32 + (((lane >> 3) & 1) << 4);
                unsigned r[4];
                ldm4t(r, kvb + 8192 + SW128(krow * 128 + dby));
                v0[2*dp] = r[0]; v1[2*dp] = r[2];
                v0[2*dp+1] = r[1]; v1[2*dp+1] = r[3];
            }
            #pragma unroll
            for (int nt = 0; nt < 8; nt++)
                mma16816h(o[nt], pg[2*j], pg8[2*j], pg[2*j+1], pg8[2*j+1],
                          v0[nt], v1[nt]);
            mma16816h(lacc, pg[2*j], pg8[2*j], pg[2*j+1], pg8[2*j+1],
                      ONES, ONES);
        }

        __syncthreads();
        if (kt + 3 < NS / 64) issue_kv(st, (kt + 3) * 64);
        CP_COMMIT();
        st = (st == 2) ? 0 : st + 1;
    }

    // ---- finalize: l already fully reduced by ones-MMA ----
    const float inv0 = 1.0f / lacc[0];
    const float inv1 = 1.0f / lacc[2];
    const int qg = q0 + w * 16 + g;
    #pragma unroll
    for (int nt = 0; nt < 8; nt++) {
        const int col = h * ND + nt * 8 + 2 * c4;
        *(__half2*)&g_c16[((size_t)(b * NS + qg)) * NE + col] =
            __floats2half2_rn(o[nt][0] * inv0, o[nt][1] * inv0);
        *(__half2*)&g_c16[((size_t)(b * NS + qg + 8)) * NE + col] =
            __floats2half2_rn(o[nt][2] * inv1, o[nt][3] * inv1);
    }
}

// ---------------------------------------------------------------------------

extern "C" void kernel_launch(void* const* d_in, const int* in_sizes, int n_in,
                              void* d_out, int out_size)
{
    const float* x   = (const float*)d_in[0];
    const int*   am  = (const int*)  d_in[1];
    const float* Wq  = (const float*)d_in[2];
    const float* bq  = (const float*)d_in[3];
    const float* Wk  = (const float*)d_in[4];
    const float* bk  = (const float*)d_in[5];
    const float* Wv  = (const float*)d_in[6];
    const float* bv  = (const float*)d_in[7];
    const float* Wo  = (const float*)d_in[8];
    const float* bo  = (const float*)d_in[9];
    float* out = (float*)d_out;

    cudaFuncSetAttribute(mm_tc, cudaFuncAttributeMaxDynamicSharedMemorySize, MM_SMEM);
    cudaFuncSetAttribute(attn_kernel, cudaFuncAttributeMaxDynamicSharedMemorySize, AT_SMEM);

    conv_x_kernel<<<NM * NE / 1024, 256>>>(x);
    conv_w_kernel<<<dim3(NE * NE / 1024, 4), 256>>>(Wq, Wk, Wv, Wo);

    mm_tc<<<dim3(NM / 128, NE / 128, 3), 256, MM_SMEM>>>(0, bq, bk, bv, nullptr);

    attn_kernel<<<dim3(NS / 128, NH, NB), 256, AT_SMEM>>>(am);

    mm_tc<<<dim3(NM / 128, NE / 128, 1), 256, MM_SMEM>>>(1, bo, nullptr, nullptr, out);
}